// round 14
// baseline (speedup 1.0000x reference)
#include <cuda_runtime.h>
#include <cuda_fp16.h>
#include <math.h>
#include <stdint.h>

#define THREADS 256
#define FA_THREADS 128
constexpr int Bb  = 4;
constexpr int Ss  = 1024;
constexpr int Hh  = 1024;
constexpr int Nn  = 16;
constexpr int Dd  = 64;
constexpr int FFd = 4096;
constexpr float SCALE = 0.125f;
constexpr float LOG2E = 1.4426950408889634f;
constexpr float EPSLN = 1e-5f;

// ---------------- scratch -----------------------------------------------------------
__device__ __half g_wpack[1024 * 5120];
__device__ __half g_xt  [Bb * Ss * Hh];
__device__ __half g_woh [Hh * Hh];
__device__ __half g_w1h [Hh * FFd];
__device__ __half g_w2h [FFd * Hh];
__device__ __half g_q[Bb * Nn * Ss * 128];
__device__ __half g_k[Bb * Nn * Ss * 128];
__device__ __half g_v[Bb * Nn * Ss * Dd];
__device__ __half g_concat[Bb * Ss * Hh];
__device__ __half g_h1h[Bb * Ss * Hh];
__device__ float  g_tmp[Bb * Ss * Hh];
__device__ __half g_ff[(size_t)Bb * Ss * FFd];

// ---------------- helpers ------------------------------------------------------------
__device__ __forceinline__ uint32_t smem_u32(const void* p) {
    return (uint32_t)__cvta_generic_to_shared(p);
}
__device__ __forceinline__ void cp16(uint32_t dst, const void* src) {
    asm volatile("cp.async.cg.shared.global [%0], [%1], 16;" :: "r"(dst), "l"(src));
}
__device__ __forceinline__ void cp_commit() {
    asm volatile("cp.async.commit_group;");
}
template<int N> __device__ __forceinline__ void cp_wait() {
    asm volatile("cp.async.wait_group %0;" :: "n"(N));
}
__device__ __forceinline__ void mma16816(float (&c)[4], const uint32_t (&a)[4],
                                         const uint32_t (&b)[2]) {
    asm volatile(
        "mma.sync.aligned.m16n8k16.row.col.f32.f16.f16.f32 "
        "{%0,%1,%2,%3}, {%4,%5,%6,%7}, {%8,%9}, {%0,%1,%2,%3};"
        : "+f"(c[0]), "+f"(c[1]), "+f"(c[2]), "+f"(c[3])
        : "r"(a[0]), "r"(a[1]), "r"(a[2]), "r"(a[3]), "r"(b[0]), "r"(b[1]));
}
__device__ __forceinline__ void ldsm4(uint32_t (&r)[4], uint32_t addr) {
    asm volatile("ldmatrix.sync.aligned.m8n8.x4.shared.b16 {%0,%1,%2,%3}, [%4];"
        : "=r"(r[0]), "=r"(r[1]), "=r"(r[2]), "=r"(r[3]) : "r"(addr));
}
__device__ __forceinline__ void ldsm4t4(uint32_t (&r)[4], uint32_t addr) {
    asm volatile("ldmatrix.sync.aligned.m8n8.x4.trans.shared.b16 {%0,%1,%2,%3}, [%4];"
        : "=r"(r[0]), "=r"(r[1]), "=r"(r[2]), "=r"(r[3]) : "r"(addr));
}
__device__ __forceinline__ void ldsm2t(uint32_t (&r)[2], uint32_t addr) {
    asm volatile("ldmatrix.sync.aligned.m8n8.x2.trans.shared.b16 {%0,%1}, [%2];"
        : "=r"(r[0]), "=r"(r[1]) : "r"(addr));
}
__device__ __forceinline__ uint32_t h2u(__half2 h) {
    return *reinterpret_cast<uint32_t*>(&h);
}
__device__ __forceinline__ float ex2f(float x) {
    float r;
    asm("ex2.approx.ftz.f32 %0, %1;" : "=f"(r) : "f"(x));
    return r;
}

// ---------------- fp16 tensor-core GEMM core, templated BM ---------------------------
// D[BM x 128] = A[m0..,K] @ B[K, n0..]; A [M][K], B [K][N] fp16. 8 warps (2 x 4),
// warp tile (BM/2) x 32. BK=64 double-buffered cp.async.
constexpr int hLA  = 72;
constexpr int hLB  = 136;
constexpr int hBSZ = 64 * hLB;

template<int BM, int KTOT, typename Epi>
__device__ __forceinline__ void hgemm(
    const __half* __restrict__ A, int lda,
    const __half* __restrict__ B, int ldb,
    int m0, int n0, Epi epi)
{
    constexpr int MT   = BM / 32;            // 4 for BM=128, 2 for BM=64
    constexpr int ASZ  = BM * hLA;
    constexpr int BUF  = ASZ + hBSZ;
    constexpr int A_LD = BM * 8 / THREADS;   // cp16 per thread for A

    extern __shared__ __half hsm[];
    const int tid = threadIdx.x, lane = tid & 31, wid = tid >> 5;
    const int wm = wid >> 2, wn = wid & 3;
    const int lrow = lane & 15, lhi = (lane >> 4) & 1;

    auto load_tile = [&](int buf, int kc) {
        __half* a = hsm + buf * BUF;
        __half* b = a + ASZ;
        uint32_t ab = smem_u32(a), bb = smem_u32(b);
        #pragma unroll
        for (int u = 0; u < A_LD; ++u) {
            int idx = tid + u * THREADS;
            int m = idx >> 3, kq = idx & 7;
            cp16(ab + (m * hLA + kq * 8) * 2,
                 A + (size_t)(m0 + m) * lda + kc * 64 + kq * 8);
        }
        #pragma unroll
        for (int u = 0; u < 4; ++u) {
            int idx = tid + u * THREADS;
            int r = idx >> 4, q = idx & 15;
            cp16(bb + (r * hLB + q * 8) * 2,
                 B + (size_t)(kc * 64 + r) * ldb + n0 + q * 8);
        }
    };

    float acc[MT][4][4] = {};

    auto compute = [&](int buf) {
        __half* a = hsm + buf * BUF;
        __half* b = a + ASZ;
        uint32_t ab = smem_u32(a), bb = smem_u32(b);
        #pragma unroll
        for (int ks = 0; ks < 4; ++ks) {
            int kk = ks * 16;
            uint32_t af[MT][4];
            #pragma unroll
            for (int i = 0; i < MT; ++i) {
                int row = wm * (MT * 16) + i * 16 + lrow;
                ldsm4(af[i], ab + (row * hLA + kk + lhi * 8) * 2);
            }
            #pragma unroll
            for (int p = 0; p < 2; ++p) {
                uint32_t bf[4];
                ldsm4t4(bf, bb + ((kk + lrow) * hLB + wn * 32 + p * 16 + lhi * 8) * 2);
                uint32_t b0[2] = { bf[0], bf[1] };
                uint32_t b1[2] = { bf[2], bf[3] };
                #pragma unroll
                for (int i = 0; i < MT; ++i) {
                    mma16816(acc[i][2 * p],     af[i], b0);
                    mma16816(acc[i][2 * p + 1], af[i], b1);
                }
            }
        }
    };

    constexpr int T = KTOT / 64;
    load_tile(0, 0);
    cp_commit();
    for (int i = 0; i < T; ++i) {
        cp_wait<0>();
        __syncthreads();
        if (i + 1 < T) { load_tile((i + 1) & 1, i + 1); cp_commit(); }
        compute(i & 1);
    }

    const int g = lane >> 2, t = lane & 3;
    #pragma unroll
    for (int i = 0; i < MT; ++i) {
        int r0 = m0 + (wm * MT + i) * 16 + g;
        #pragma unroll
        for (int j = 0; j < 4; ++j) {
            int c0 = n0 + (wn * 4 + j) * 8 + 2 * t;
            epi(r0,     c0, acc[i][j][0], acc[i][j][1]);
            epi(r0 + 8, c0, acc[i][j][2], acc[i][j][3]);
        }
    }
}

constexpr size_t SM_HGEMM   = (size_t)2 * (128 * hLA + hBSZ) * sizeof(__half); // 71680
constexpr size_t SM_HGEMM64 = (size_t)2 * (64 * hLA + hBSZ) * sizeof(__half);  // 53248

// ---------------- merged prepass ------------------------------------------------------
constexpr int N4_X  = Bb * Ss * Hh / 4;
constexpr int N4_WO = Hh * Hh / 4;
constexpr int N4_W1 = Hh * FFd / 4;
constexpr int N4_ALL = N4_X + N4_WO + 2 * N4_W1;
constexpr int N4_RP  = 1024 * 5120 / 4;
constexpr int N4_TOT = N4_ALL + N4_RP;

__global__ __launch_bounds__(THREADS) void prepass_kernel(
    const float4* __restrict__ x,  const float4* __restrict__ Wo,
    const float4* __restrict__ W1, const float4* __restrict__ W2,
    const float* __restrict__ Wqr, const float* __restrict__ Wqi,
    const float* __restrict__ Wkr, const float* __restrict__ Wki,
    const float* __restrict__ Wv)
{
    int base = blockIdx.x * (THREADS * 4) + threadIdx.x;
    #pragma unroll
    for (int u = 0; u < 4; ++u) {
        int i = base + u * THREADS;
        if (i >= N4_TOT) return;
        if (i < N4_ALL) {
            const float4* src;
            uint2* dst;
            int j;
            if (i < N4_X) {
                src = x;  dst = (uint2*)g_xt;  j = i;
            } else if (i < N4_X + N4_WO) {
                src = Wo; dst = (uint2*)g_woh; j = i - N4_X;
            } else if (i < N4_X + N4_WO + N4_W1) {
                src = W1; dst = (uint2*)g_w1h; j = i - N4_X - N4_WO;
            } else {
                src = W2; dst = (uint2*)g_w2h; j = i - N4_X - N4_WO - N4_W1;
            }
            float4 v = src[j];
            dst[j] = make_uint2(h2u(__floats2half2_rn(v.x, v.y)),
                                h2u(__floats2half2_rn(v.z, v.w)));
        } else {
            int idx = i - N4_ALL;
            int col4 = idx % 1280;
            int k    = idx / 1280;
            int c = col4 * 4;
            int p = c >> 10, n = (c >> 6) & 15, d = c & 63;
            const float* W = (p == 0) ? Wqr : (p == 1) ? Wqi : (p == 2) ? Wkr
                            : (p == 3) ? Wki : Wv;
            float4 v = *reinterpret_cast<const float4*>(
                W + (((size_t)n) << 16) + (size_t)k * 64 + d);
            *reinterpret_cast<uint2*>(g_wpack + (size_t)k * 5120 + c) =
                make_uint2(h2u(__floats2half2_rn(v.x, v.y)),
                           h2u(__floats2half2_rn(v.z, v.w)));
        }
    }
}

// ---------------- GEMM kernels --------------------------------------------------------
__global__ __launch_bounds__(THREADS, 2) void hproj_kernel(
    const float* __restrict__ bqr, const float* __restrict__ bqi,
    const float* __restrict__ bkr, const float* __restrict__ bki,
    const float* __restrict__ bvv,
    const float* __restrict__ pqr, const float* __restrict__ pqi,
    const float* __restrict__ pkr, const float* __restrict__ pki)
{
    constexpr float QSC = SCALE * LOG2E;
    int m0 = blockIdx.y * 128, n0 = blockIdx.x * 128;
    hgemm<128, 1024>(g_xt, Hh, g_wpack, 5120, m0, n0,
        [&](int row, int col, float v0, float v1) {
            int p = col >> 10, n = (col >> 6) & 15, d = col & 63;
            int bb = row >> 10, s = row & 1023;
            size_t pidx = (((size_t)n << 10) + s) * Dd + d;
            size_t rowoff = (((size_t)(bb * Nn + n)) << 10) + s;
            float x0, x1;
            __half* dst;
            if (p == 0) {
                x0 = ((v0 + bqr[n * Dd + d])     * SCALE + pqr[pidx])     * QSC;
                x1 = ((v1 + bqr[n * Dd + d + 1]) * SCALE + pqr[pidx + 1]) * QSC;
                dst = g_q + rowoff * 128 + d;
            } else if (p == 1) {
                x0 = -(((v0 + bqi[n * Dd + d])     * SCALE + pqi[pidx])     * QSC);
                x1 = -(((v1 + bqi[n * Dd + d + 1]) * SCALE + pqi[pidx + 1]) * QSC);
                dst = g_q + rowoff * 128 + 64 + d;
            } else if (p == 2) {
                x0 = v0 + bkr[n * Dd + d]     + pkr[pidx];
                x1 = v1 + bkr[n * Dd + d + 1] + pkr[pidx + 1];
                dst = g_k + rowoff * 128 + d;
            } else if (p == 3) {
                x0 = v0 + bki[n * Dd + d]     + pki[pidx];
                x1 = v1 + bki[n * Dd + d + 1] + pki[pidx + 1];
                dst = g_k + rowoff * 128 + 64 + d;
            } else {
                x0 = v0 + bvv[n * Dd + d];
                x1 = v1 + bvv[n * Dd + d + 1];
                dst = g_v + rowoff * Dd + d;
            }
            *reinterpret_cast<__half2*>(dst) = __floats2half2_rn(x0, x1);
        });
}

__global__ __launch_bounds__(THREADS) void hwo_kernel(
    const float* __restrict__ bo, const float* __restrict__ x)
{
    int m0 = blockIdx.y * 64, n0 = blockIdx.x * 128;
    hgemm<64, 1024>(g_concat, Hh, g_woh, Hh, m0, n0,
        [&](int row, int c0, float v0, float v1) {
            size_t o = (size_t)row * Hh + c0;
            g_tmp[o]     = v0 + bo[c0]     + x[o];
            g_tmp[o + 1] = v1 + bo[c0 + 1] + x[o + 1];
        });
}

__global__ __launch_bounds__(THREADS, 2) void hff1_kernel(const float* __restrict__ b1)
{
    int m0 = blockIdx.y * 128, n0 = blockIdx.x * 128;
    hgemm<128, 1024>(g_h1h, Hh, g_w1h, FFd, m0, n0,
        [&](int row, int c0, float v0, float v1) {
            size_t o = (size_t)row * FFd + c0;
            *reinterpret_cast<__half2*>(g_ff + o) = __floats2half2_rn(
                fmaxf(v0 + b1[c0], 0.f), fmaxf(v1 + b1[c0 + 1], 0.f));
        });
}

__global__ __launch_bounds__(THREADS) void hff2_kernel(const float* __restrict__ b2)
{
    int m0 = blockIdx.y * 64, n0 = blockIdx.x * 128;
    hgemm<64, 4096>(g_ff, FFd, g_w2h, Hh, m0, n0,
        [&](int row, int c0, float v0, float v1) {
            size_t o = (size_t)row * Hh + c0;
            __half2 hh = *reinterpret_cast<const __half2*>(g_h1h + o);
            g_tmp[o]     = v0 + b2[c0]     + __low2float(hh);
            g_tmp[o + 1] = v1 + b2[c0 + 1] + __high2float(hh);
        });
}

// ---------------- flash attention: 128-thr CTAs, 32 q-rows/warp, 2 CTA/SM -------------
constexpr int fQ0   = 0;
constexpr int fKV0  = 17408;
constexpr int fKVSZ = 13312;
constexpr int fVOFF = 8704;
constexpr size_t SM_FLASH = (size_t)(17408 + 2 * 13312) * sizeof(__half); // 88064 B

__global__ __launch_bounds__(FA_THREADS, 2) void flash_attn_kernel()
{
    extern __shared__ __half hsm[];
    const int tid = threadIdx.x, lane = tid & 31, wid = tid >> 5;
    const int g = lane >> 2, t = lane & 3;
    const int lrow = lane & 15, lhi = (lane >> 4) & 1;
    const int bh = blockIdx.y, b = bh >> 4, head = bh & 15;
    const int m0 = blockIdx.x * 128;

    const __half* Qg = g_q + (size_t)bh * Ss * 128;
    const __half* Kg = g_k + (size_t)bh * Ss * 128;
    const __half* Vg = g_v + (size_t)bh * Ss * Dd;

    const uint32_t sQ = smem_u32(hsm + fQ0);

    #pragma unroll
    for (int u = 0; u < 16; ++u) {
        int idx = tid + u * FA_THREADS;
        int m = idx >> 4, q = idx & 15;
        cp16(sQ + (m * 136 + q * 8) * 2, Qg + (size_t)(m0 + m) * 128 + q * 8);
    }

    {
        int buf = tid >> 6, r = tid & 63;
        uint4* pad = reinterpret_cast<uint4*>(
            hsm + fKV0 + buf * fKVSZ + fVOFF + r * 72 + 64);
        *pad = make_uint4(0x00003C00u, 0u, 0u, 0u);
    }

    auto load_kv = [&](int kt, int buf) {
        uint32_t sK = smem_u32(hsm + fKV0 + buf * fKVSZ);
        uint32_t sV = sK + fVOFF * 2;
        const __half* kp = Kg + (size_t)kt * 64 * 128;
        const __half* vp = Vg + (size_t)kt * 64 * Dd;
        #pragma unroll
        for (int u = 0; u < 8; ++u) {
            int idx = tid + u * FA_THREADS;
            int r = idx >> 4, q = idx & 15;
            cp16(sK + (r * 136 + q * 8) * 2, kp + (size_t)r * 128 + q * 8);
        }
        #pragma unroll
        for (int u = 0; u < 4; ++u) {
            int idx = tid + u * FA_THREADS;
            int r = idx >> 3, q = idx & 7;
            cp16(sV + (r * 72 + q * 8) * 2, vp + (size_t)r * Dd + q * 8);
        }
    };
    load_kv(0, 0);
    cp_commit();

    float m_run[2][2] = {{-1e30f, -1e30f}, {-1e30f, -1e30f}};
    float acc_o[2][8][4] = {};
    float acc_l[2][4] = {};
    const int mq = wid * 32;

    constexpr int NT = Ss / 64;
    for (int kt = 0; kt < NT; ++kt) {
        const int buf = kt & 1;
        cp_wait<0>();
        __syncthreads();
        if (kt + 1 < NT) { load_kv(kt + 1, buf ^ 1); cp_commit(); }

        const uint32_t sK = smem_u32(hsm + fKV0 + buf * fKVSZ);
        const uint32_t sV = sK + fVOFF * 2;

        float acc_s[2][8][4] = {};
        #pragma unroll
        for (int ks = 0; ks < 8; ++ks) {
            uint32_t qf[2][4];
            #pragma unroll
            for (int si = 0; si < 2; ++si)
                ldsm4(qf[si], sQ + ((mq + si * 16 + lrow) * 136 + ks * 16 + lhi * 8) * 2);
            #pragma unroll
            for (int p = 0; p < 4; ++p) {
                uint32_t bf[4];
                ldsm4(bf, sK + ((p * 16 + lrow) * 136 + ks * 16 + lhi * 8) * 2);
                uint32_t b0[2] = { bf[0], bf[2] };
                uint32_t b1[2] = { bf[1], bf[3] };
                #pragma unroll
                for (int si = 0; si < 2; ++si) {
                    mma16816(acc_s[si][2 * p],     qf[si], b0);
                    mma16816(acc_s[si][2 * p + 1], qf[si], b1);
                }
            }
        }

        uint32_t pf[2][4][4];
        #pragma unroll
        for (int si = 0; si < 2; ++si) {
            float tm0 = -1e30f, tm1 = -1e30f;
            #pragma unroll
            for (int j = 0; j < 8; ++j) {
                tm0 = fmaxf(tm0, fmaxf(acc_s[si][j][0], acc_s[si][j][1]));
                tm1 = fmaxf(tm1, fmaxf(acc_s[si][j][2], acc_s[si][j][3]));
            }
            #pragma unroll
            for (int o = 1; o <= 2; o <<= 1) {
                tm0 = fmaxf(tm0, __shfl_xor_sync(0xffffffffu, tm0, o));
                tm1 = fmaxf(tm1, __shfl_xor_sync(0xffffffffu, tm1, o));
            }
            float mn0 = fmaxf(m_run[si][0], tm0), mn1 = fmaxf(m_run[si][1], tm1);
            float sc0 = ex2f(m_run[si][0] - mn0), sc1 = ex2f(m_run[si][1] - mn1);
            m_run[si][0] = mn0; m_run[si][1] = mn1;

            #pragma unroll
            for (int j = 0; j < 8; ++j) {
                acc_s[si][j][0] = ex2f(acc_s[si][j][0] - mn0);
                acc_s[si][j][1] = ex2f(acc_s[si][j][1] - mn0);
                acc_s[si][j][2] = ex2f(acc_s[si][j][2] - mn1);
                acc_s[si][j][3] = ex2f(acc_s[si][j][3] - mn1);
            }
            #pragma unroll
            for (int j = 0; j < 8; ++j) {
                acc_o[si][j][0] *= sc0; acc_o[si][j][1] *= sc0;
                acc_o[si][j][2] *= sc1; acc_o[si][j][3] *= sc1;
            }
            acc_l[si][0] *= sc0; acc_l[si][1] *= sc0;
            acc_l[si][2] *= sc1; acc_l[si][3] *= sc1;

            #pragma unroll
            for (int k2 = 0; k2 < 4; ++k2) {
                pf[si][k2][0] = h2u(__floats2half2_rn(acc_s[si][2 * k2][0],     acc_s[si][2 * k2][1]));
                pf[si][k2][1] = h2u(__floats2half2_rn(acc_s[si][2 * k2][2],     acc_s[si][2 * k2][3]));
                pf[si][k2][2] = h2u(__floats2half2_rn(acc_s[si][2 * k2 + 1][0], acc_s[si][2 * k2 + 1][1]));
                pf[si][k2][3] = h2u(__floats2half2_rn(acc_s[si][2 * k2 + 1][2], acc_s[si][2 * k2 + 1][3]));
            }
        }

        #pragma unroll
        for (int ks = 0; ks < 4; ++ks) {
            #pragma unroll
            for (int p = 0; p < 4; ++p) {
                uint32_t bf[4];
                ldsm4t4(bf, sV + ((ks * 16 + lrow) * 72 + p * 16 + lhi * 8) * 2);
                uint32_t b0[2] = { bf[0], bf[1] };
                uint32_t b1[2] = { bf[2], bf[3] };
                #pragma unroll
                for (int si = 0; si < 2; ++si) {
                    mma16816(acc_o[si][2 * p],     pf[si][ks], b0);
                    mma16816(acc_o[si][2 * p + 1], pf[si][ks], b1);
                }
            }
            uint32_t bl[2];
            ldsm2t(bl, sV + ((ks * 16 + lrow) * 72 + 64) * 2);
            #pragma unroll
            for (int si = 0; si < 2; ++si)
                mma16816(acc_l[si], pf[si][ks], bl);
        }
    }

    #pragma unroll
    for (int si = 0; si < 2; ++si) {
        float l0 = __shfl_sync(0xffffffffu, acc_l[si][0], lane & ~3);
        float l1 = __shfl_sync(0xffffffffu, acc_l[si][2], lane & ~3);
        float inv0 = 1.0f / l0, inv1 = 1.0f / l1;
        int s0 = m0 + mq + si * 16 + g;
        #pragma unroll
        for (int j = 0; j < 8; ++j) {
            int c = j * 8 + 2 * t;
            __half* o0 = g_concat + ((size_t)(b * Ss + s0)) * Hh + head * Dd + c;
            __half* o1 = g_concat + ((size_t)(b * Ss + s0 + 8)) * Hh + head * Dd + c;
            *reinterpret_cast<__half2*>(o0) =
                __floats2half2_rn(acc_o[si][j][0] * inv0, acc_o[si][j][1] * inv0);
            *reinterpret_cast<__half2*>(o1) =
                __floats2half2_rn(acc_o[si][j][2] * inv1, acc_o[si][j][3] * inv1);
        }
    }
}

// ---------------- LayerNorms ----------------------------------------------------------
__global__ __launch_bounds__(THREADS) void layernorm1_kernel(
    const float* __restrict__ gw, const float* __restrict__ bw)
{
    int row = blockIdx.x;
    const float4* rp = reinterpret_cast<const float4*>(g_tmp + (size_t)row * Hh);
    float4 v = rp[threadIdx.x];
    float s  = v.x + v.y + v.z + v.w;
    float s2 = v.x * v.x + v.y * v.y + v.z * v.z + v.w * v.w;
    #pragma unroll
    for (int o = 16; o; o >>= 1) {
        s  += __shfl_xor_sync(0xffffffffu, s,  o);
        s2 += __shfl_xor_sync(0xffffffffu, s2, o);
    }
    __shared__ float rs[8], rs2[8];
    int lane = threadIdx.x & 31, wid = threadIdx.x >> 5;
    if (lane == 0) { rs[wid] = s; rs2[wid] = s2; }
    __syncthreads();
    s = 0.f; s2 = 0.f;
    #pragma unroll
    for (int i = 0; i < 8; ++i) { s += rs[i]; s2 += rs2[i]; }
    float mu  = s  * (1.0f / Hh);
    float var = s2 * (1.0f / Hh) - mu * mu;
    float inv = rsqrtf(var + EPSLN);
    float4 g4 = reinterpret_cast<const float4*>(gw)[threadIdx.x];
    float4 b4 = reinterpret_cast<const float4*>(bw)[threadIdx.x];
    float4 o4;
    o4.x = (v.x - mu) * inv * g4.x + b4.x;
    o4.y = (v.y - mu) * inv * g4.y + b4.y;
    o4.z = (v.z - mu) * inv * g4.z + b4.z;
    o4.w = (v.w - mu) * inv * g4.w + b4.w;
    uint2 hh = make_uint2(h2u(__floats2half2_rn(o4.x, o4.y)),
                          h2u(__floats2half2_rn(o4.z, o4.w)));
    reinterpret_cast<uint2*>(g_h1h + (size_t)row * Hh)[threadIdx.x] = hh;
}

__global__ __launch_bounds__(THREADS) void layernorm2_kernel(
    const float* __restrict__ gw, const float* __restrict__ bw,
    float* __restrict__ out)
{
    int row = blockIdx.x;
    const float4* rp = reinterpret_cast<const float4*>(g_tmp + (size_t)row * Hh);
    float4 v = rp[threadIdx.x];
    float s  = v.x + v.y + v.z + v.w;
    float s2 = v.x * v.x + v.y * v.y + v.z * v.z + v.w * v.w;
    #pragma unroll
    for (int o = 16; o; o >>= 1) {
        s  += __shfl_xor_sync(0xffffffffu, s,  o);
        s2 += __shfl_xor_sync(0xffffffffu, s2, o);
    }
    __shared__ float rs[8], rs2[8];
    int lane = threadIdx.x & 31, wid = threadIdx.x >> 5;
    if (lane == 0) { rs[wid] = s; rs2[wid] = s2; }
    __syncthreads();
    s = 0.f; s2 = 0.f;
    #pragma unroll
    for (int i = 0; i < 8; ++i) { s += rs[i]; s2 += rs2[i]; }
    float mu  = s  * (1.0f / Hh);
    float var = s2 * (1.0f / Hh) - mu * mu;
    float inv = rsqrtf(var + EPSLN);
    float4 g4 = reinterpret_cast<const float4*>(gw)[threadIdx.x];
    float4 b4 = reinterpret_cast<const float4*>(bw)[threadIdx.x];
    float4 o4;
    o4.x = (v.x - mu) * inv * g4.x + b4.x;
    o4.y = (v.y - mu) * inv * g4.y + b4.y;
    o4.z = (v.z - mu) * inv * g4.z + b4.z;
    o4.w = (v.w - mu) * inv * g4.w + b4.w;
    reinterpret_cast<float4*>(out + (size_t)row * Hh)[threadIdx.x] = o4;
}

// ---------------- entry -----------------------------------------------------------------
extern "C" void kernel_launch(void* const* d_in, const int* in_sizes, int n_in,
                              void* d_out, int out_size)
{
    const float* x   = (const float*)d_in[0];
    const float* Wqr = (const float*)d_in[1];
    const float* Wqi = (const float*)d_in[2];
    const float* bqr = (const float*)d_in[3];
    const float* bqi = (const float*)d_in[4];
    const float* Wkr = (const float*)d_in[5];
    const float* Wki = (const float*)d_in[6];
    const float* bkr = (const float*)d_in[7];
    const float* bki = (const float*)d_in[8];
    const float* Wv  = (const float*)d_in[9];
    const float* bvv = (const float*)d_in[10];
    const float* pqr = (const float*)d_in[11];
    const float* pqi = (const float*)d_in[12];
    const float* pkr = (const float*)d_in[13];
    const float* pki = (const float*)d_in[14];
    const float* Wo  = (const float*)d_in[15];
    const float* bo  = (const float*)d_in[16];
    const float* W1  = (const float*)d_in[17];
    const float* b1  = (const float*)d_in[18];
    const float* W2  = (const float*)d_in[19];
    const float* b2  = (const float*)d_in[20];
    const float* g1  = (const float*)d_in[21];
    const float* be1 = (const float*)d_in[22];
    const float* g2  = (const float*)d_in[23];
    const float* be2 = (const float*)d_in[24];
    float* out = (float*)d_out;

    static bool attr_done = false;
    if (!attr_done) {
        cudaFuncSetAttribute(hproj_kernel,
            cudaFuncAttributeMaxDynamicSharedMemorySize, (int)SM_HGEMM);
        cudaFuncSetAttribute(hwo_kernel,
            cudaFuncAttributeMaxDynamicSharedMemorySize, (int)SM_HGEMM64);
        cudaFuncSetAttribute(hff1_kernel,
            cudaFuncAttributeMaxDynamicSharedMemorySize, (int)SM_HGEMM);
        cudaFuncSetAttribute(hff2_kernel,
            cudaFuncAttributeMaxDynamicSharedMemorySize, (int)SM_HGEMM64);
        cudaFuncSetAttribute(flash_attn_kernel,
            cudaFuncAttributeMaxDynamicSharedMemorySize, (int)SM_FLASH);
        attr_done = true;
    }

    const int U4 = THREADS * 4;
    prepass_kernel<<<(N4_TOT + U4 - 1) / U4, THREADS>>>(
        (const float4*)x, (const float4*)Wo, (const float4*)W1, (const float4*)W2,
        Wqr, Wqi, Wkr, Wki, Wv);

    hproj_kernel<<<dim3(5120 / 128, (Bb * Ss) / 128), THREADS, SM_HGEMM>>>(
        bqr, bqi, bkr, bki, bvv, pqr, pqi, pkr, pki);
    flash_attn_kernel<<<dim3(Ss / 128, Bb * Nn), FA_THREADS, SM_FLASH>>>();
    hwo_kernel<<<dim3(Hh / 128, (Bb * Ss) / 64), THREADS, SM_HGEMM64>>>(bo, x);
    layernorm1_kernel<<<Bb * Ss, THREADS>>>(g1, be1);
    hff1_kernel<<<dim3(FFd / 128, (Bb * Ss) / 128), THREADS, SM_HGEMM>>>(b1);
    hff2_kernel<<<dim3(Hh / 128, (Bb * Ss) / 64), THREADS, SM_HGEMM64>>>(b2);
    layernorm2_kernel<<<Bb * Ss, THREADS>>>(g2, be2, out);
}

// round 15
// speedup vs baseline: 1.0278x; 1.0278x over previous
#include <cuda_runtime.h>
#include <cuda_fp16.h>
#include <math.h>
#include <stdint.h>

#define THREADS 256
#define FA_THREADS 128
constexpr int Bb  = 4;
constexpr int Ss  = 1024;
constexpr int Hh  = 1024;
constexpr int Nn  = 16;
constexpr int Dd  = 64;
constexpr int FFd = 4096;
constexpr float SCALE = 0.125f;
constexpr float LOG2E = 1.4426950408889634f;
constexpr float EPSLN = 1e-5f;

// ---------------- scratch -----------------------------------------------------------
__device__ __half g_wpack[1024 * 5120];
__device__ __half g_xt  [Bb * Ss * Hh];
__device__ __half g_woh [Hh * Hh];
__device__ __half g_w1h [Hh * FFd];
__device__ __half g_w2h [FFd * Hh];
__device__ __half g_q[Bb * Nn * Ss * 128];
__device__ __half g_k[Bb * Nn * Ss * 128];
__device__ __half g_v[Bb * Nn * Ss * Dd];
__device__ __half g_concat[Bb * Ss * Hh];
__device__ __half g_h1h[Bb * Ss * Hh];
__device__ float  g_tmp[Bb * Ss * Hh];
__device__ __half g_ff[(size_t)Bb * Ss * FFd];

// ---------------- helpers ------------------------------------------------------------
__device__ __forceinline__ uint32_t smem_u32(const void* p) {
    return (uint32_t)__cvta_generic_to_shared(p);
}
__device__ __forceinline__ void cp16(uint32_t dst, const void* src) {
    asm volatile("cp.async.cg.shared.global [%0], [%1], 16;" :: "r"(dst), "l"(src));
}
__device__ __forceinline__ void cp_commit() {
    asm volatile("cp.async.commit_group;");
}
template<int N> __device__ __forceinline__ void cp_wait() {
    asm volatile("cp.async.wait_group %0;" :: "n"(N));
}
__device__ __forceinline__ void mma16816(float (&c)[4], const uint32_t (&a)[4],
                                         const uint32_t (&b)[2]) {
    asm volatile(
        "mma.sync.aligned.m16n8k16.row.col.f32.f16.f16.f32 "
        "{%0,%1,%2,%3}, {%4,%5,%6,%7}, {%8,%9}, {%0,%1,%2,%3};"
        : "+f"(c[0]), "+f"(c[1]), "+f"(c[2]), "+f"(c[3])
        : "r"(a[0]), "r"(a[1]), "r"(a[2]), "r"(a[3]), "r"(b[0]), "r"(b[1]));
}
__device__ __forceinline__ void ldsm4(uint32_t (&r)[4], uint32_t addr) {
    asm volatile("ldmatrix.sync.aligned.m8n8.x4.shared.b16 {%0,%1,%2,%3}, [%4];"
        : "=r"(r[0]), "=r"(r[1]), "=r"(r[2]), "=r"(r[3]) : "r"(addr));
}
__device__ __forceinline__ void ldsm4t4(uint32_t (&r)[4], uint32_t addr) {
    asm volatile("ldmatrix.sync.aligned.m8n8.x4.trans.shared.b16 {%0,%1,%2,%3}, [%4];"
        : "=r"(r[0]), "=r"(r[1]), "=r"(r[2]), "=r"(r[3]) : "r"(addr));
}
__device__ __forceinline__ void ldsm2t(uint32_t (&r)[2], uint32_t addr) {
    asm volatile("ldmatrix.sync.aligned.m8n8.x2.trans.shared.b16 {%0,%1}, [%2];"
        : "=r"(r[0]), "=r"(r[1]) : "r"(addr));
}
__device__ __forceinline__ uint32_t h2u(__half2 h) {
    return *reinterpret_cast<uint32_t*>(&h);
}
__device__ __forceinline__ float ex2f(float x) {
    float r;
    asm("ex2.approx.ftz.f32 %0, %1;" : "=f"(r) : "f"(x));
    return r;
}

// ---------------- fp16 tensor-core GEMM core (BM=128, B in [K][N]) -------------------
constexpr int hLA  = 72;
constexpr int hLB  = 136;
constexpr int hASZ = 128 * hLA;
constexpr int hBSZ = 64 * hLB;
constexpr int hBUF = hASZ + hBSZ;
constexpr size_t SM_HGEMM = (size_t)2 * hBUF * sizeof(__half);   // 71680 B

template<int KTOT, typename Epi>
__device__ __forceinline__ void hgemm(
    const __half* __restrict__ A, int lda,
    const __half* __restrict__ B, int ldb,
    int m0, int n0, Epi epi)
{
    extern __shared__ __half hsm[];
    const int tid = threadIdx.x, lane = tid & 31, wid = tid >> 5;
    const int wm = wid >> 2, wn = wid & 3;
    const int lrow = lane & 15, lhi = (lane >> 4) & 1;

    auto load_tile = [&](int buf, int kc) {
        __half* a = hsm + buf * hBUF;
        __half* b = a + hASZ;
        uint32_t ab = smem_u32(a), bb = smem_u32(b);
        #pragma unroll
        for (int u = 0; u < 4; ++u) {
            int idx = tid + u * THREADS;
            int m = idx >> 3, kq = idx & 7;
            cp16(ab + (m * hLA + kq * 8) * 2,
                 A + (size_t)(m0 + m) * lda + kc * 64 + kq * 8);
        }
        #pragma unroll
        for (int u = 0; u < 4; ++u) {
            int idx = tid + u * THREADS;
            int r = idx >> 4, q = idx & 15;
            cp16(bb + (r * hLB + q * 8) * 2,
                 B + (size_t)(kc * 64 + r) * ldb + n0 + q * 8);
        }
    };

    float acc[4][4][4] = {};

    auto compute = [&](int buf) {
        __half* a = hsm + buf * hBUF;
        __half* b = a + hASZ;
        uint32_t ab = smem_u32(a), bb = smem_u32(b);
        #pragma unroll
        for (int ks = 0; ks < 4; ++ks) {
            int kk = ks * 16;
            uint32_t af[4][4];
            #pragma unroll
            for (int i = 0; i < 4; ++i) {
                int row = wm * 64 + i * 16 + lrow;
                ldsm4(af[i], ab + (row * hLA + kk + lhi * 8) * 2);
            }
            #pragma unroll
            for (int p = 0; p < 2; ++p) {
                uint32_t bf[4];
                ldsm4t4(bf, bb + ((kk + lrow) * hLB + wn * 32 + p * 16 + lhi * 8) * 2);
                uint32_t b0[2] = { bf[0], bf[1] };
                uint32_t b1[2] = { bf[2], bf[3] };
                #pragma unroll
                for (int i = 0; i < 4; ++i) {
                    mma16816(acc[i][2 * p],     af[i], b0);
                    mma16816(acc[i][2 * p + 1], af[i], b1);
                }
            }
        }
    };

    constexpr int T = KTOT / 64;
    load_tile(0, 0);
    cp_commit();
    for (int i = 0; i < T; ++i) {
        cp_wait<0>();
        __syncthreads();
        if (i + 1 < T) { load_tile((i + 1) & 1, i + 1); cp_commit(); }
        compute(i & 1);
    }

    const int g = lane >> 2, t = lane & 3;
    #pragma unroll
    for (int i = 0; i < 4; ++i) {
        int r0 = m0 + (wm * 4 + i) * 16 + g;
        #pragma unroll
        for (int j = 0; j < 4; ++j) {
            int c0 = n0 + (wn * 4 + j) * 8 + 2 * t;
            epi(r0,     c0, acc[i][j][0], acc[i][j][1]);
            epi(r0 + 8, c0, acc[i][j][2], acc[i][j][3]);
        }
    }
}

// ---------------- merged prepass ------------------------------------------------------
constexpr int N4_X  = Bb * Ss * Hh / 4;
constexpr int N4_WO = Hh * Hh / 4;
constexpr int N4_W1 = Hh * FFd / 4;
constexpr int N4_ALL = N4_X + N4_WO + 2 * N4_W1;
constexpr int N4_RP  = 1024 * 5120 / 4;
constexpr int N4_TOT = N4_ALL + N4_RP;

__global__ __launch_bounds__(THREADS) void prepass_kernel(
    const float4* __restrict__ x,  const float4* __restrict__ Wo,
    const float4* __restrict__ W1, const float4* __restrict__ W2,
    const float* __restrict__ Wqr, const float* __restrict__ Wqi,
    const float* __restrict__ Wkr, const float* __restrict__ Wki,
    const float* __restrict__ Wv)
{
    int base = blockIdx.x * (THREADS * 4) + threadIdx.x;
    #pragma unroll
    for (int u = 0; u < 4; ++u) {
        int i = base + u * THREADS;
        if (i >= N4_TOT) return;
        if (i < N4_ALL) {
            const float4* src;
            uint2* dst;
            int j;
            if (i < N4_X) {
                src = x;  dst = (uint2*)g_xt;  j = i;
            } else if (i < N4_X + N4_WO) {
                src = Wo; dst = (uint2*)g_woh; j = i - N4_X;
            } else if (i < N4_X + N4_WO + N4_W1) {
                src = W1; dst = (uint2*)g_w1h; j = i - N4_X - N4_WO;
            } else {
                src = W2; dst = (uint2*)g_w2h; j = i - N4_X - N4_WO - N4_W1;
            }
            float4 v = src[j];
            dst[j] = make_uint2(h2u(__floats2half2_rn(v.x, v.y)),
                                h2u(__floats2half2_rn(v.z, v.w)));
        } else {
            int idx = i - N4_ALL;
            int col4 = idx % 1280;
            int k    = idx / 1280;
            int c = col4 * 4;
            int p = c >> 10, n = (c >> 6) & 15, d = c & 63;
            const float* W = (p == 0) ? Wqr : (p == 1) ? Wqi : (p == 2) ? Wkr
                            : (p == 3) ? Wki : Wv;
            float4 v = *reinterpret_cast<const float4*>(
                W + (((size_t)n) << 16) + (size_t)k * 64 + d);
            *reinterpret_cast<uint2*>(g_wpack + (size_t)k * 5120 + c) =
                make_uint2(h2u(__floats2half2_rn(v.x, v.y)),
                           h2u(__floats2half2_rn(v.z, v.w)));
        }
    }
}

// ---------------- GEMM kernels --------------------------------------------------------
__global__ __launch_bounds__(THREADS, 2) void hproj_kernel(
    const float* __restrict__ bqr, const float* __restrict__ bqi,
    const float* __restrict__ bkr, const float* __restrict__ bki,
    const float* __restrict__ bvv,
    const float* __restrict__ pqr, const float* __restrict__ pqi,
    const float* __restrict__ pkr, const float* __restrict__ pki)
{
    constexpr float QSC = SCALE * LOG2E;
    int m0 = blockIdx.y * 128, n0 = blockIdx.x * 128;
    hgemm<1024>(g_xt, Hh, g_wpack, 5120, m0, n0,
        [&](int row, int col, float v0, float v1) {
            int p = col >> 10, n = (col >> 6) & 15, d = col & 63;
            int bb = row >> 10, s = row & 1023;
            size_t pidx = (((size_t)n << 10) + s) * Dd + d;
            size_t rowoff = (((size_t)(bb * Nn + n)) << 10) + s;
            float x0, x1;
            __half* dst;
            if (p == 0) {
                x0 = ((v0 + bqr[n * Dd + d])     * SCALE + pqr[pidx])     * QSC;
                x1 = ((v1 + bqr[n * Dd + d + 1]) * SCALE + pqr[pidx + 1]) * QSC;
                dst = g_q + rowoff * 128 + d;
            } else if (p == 1) {
                x0 = -(((v0 + bqi[n * Dd + d])     * SCALE + pqi[pidx])     * QSC);
                x1 = -(((v1 + bqi[n * Dd + d + 1]) * SCALE + pqi[pidx + 1]) * QSC);
                dst = g_q + rowoff * 128 + 64 + d;
            } else if (p == 2) {
                x0 = v0 + bkr[n * Dd + d]     + pkr[pidx];
                x1 = v1 + bkr[n * Dd + d + 1] + pkr[pidx + 1];
                dst = g_k + rowoff * 128 + d;
            } else if (p == 3) {
                x0 = v0 + bki[n * Dd + d]     + pki[pidx];
                x1 = v1 + bki[n * Dd + d + 1] + pki[pidx + 1];
                dst = g_k + rowoff * 128 + 64 + d;
            } else {
                x0 = v0 + bvv[n * Dd + d];
                x1 = v1 + bvv[n * Dd + d + 1];
                dst = g_v + rowoff * Dd + d;
            }
            *reinterpret_cast<__half2*>(dst) = __floats2half2_rn(x0, x1);
        });
}

__global__ __launch_bounds__(THREADS, 2) void hwo_kernel(
    const float* __restrict__ bo, const float* __restrict__ x)
{
    int m0 = blockIdx.y * 128, n0 = blockIdx.x * 128;
    hgemm<1024>(g_concat, Hh, g_woh, Hh, m0, n0,
        [&](int row, int c0, float v0, float v1) {
            size_t o = (size_t)row * Hh + c0;
            float2 bb = *reinterpret_cast<const float2*>(bo + c0);
            float2 xx = *reinterpret_cast<const float2*>(x + o);
            *reinterpret_cast<float2*>(g_tmp + o) =
                make_float2(v0 + bb.x + xx.x, v1 + bb.y + xx.y);
        });
}

__global__ __launch_bounds__(THREADS, 2) void hff1_kernel(const float* __restrict__ b1)
{
    int m0 = blockIdx.y * 128, n0 = blockIdx.x * 128;
    hgemm<1024>(g_h1h, Hh, g_w1h, FFd, m0, n0,
        [&](int row, int c0, float v0, float v1) {
            size_t o = (size_t)row * FFd + c0;
            float2 bb = *reinterpret_cast<const float2*>(b1 + c0);
            *reinterpret_cast<__half2*>(g_ff + o) = __floats2half2_rn(
                fmaxf(v0 + bb.x, 0.f), fmaxf(v1 + bb.y, 0.f));
        });
}

__global__ __launch_bounds__(THREADS, 2) void hff2_kernel(const float* __restrict__ b2)
{
    int m0 = blockIdx.y * 128, n0 = blockIdx.x * 128;
    hgemm<4096>(g_ff, FFd, g_w2h, Hh, m0, n0,
        [&](int row, int c0, float v0, float v1) {
            size_t o = (size_t)row * Hh + c0;
            float2 bb = *reinterpret_cast<const float2*>(b2 + c0);
            __half2 hh = *reinterpret_cast<const __half2*>(g_h1h + o);
            *reinterpret_cast<float2*>(g_tmp + o) =
                make_float2(v0 + bb.x + __low2float(hh),
                            v1 + bb.y + __high2float(hh));
        });
}

// ---------------- flash attention: 128-thr CTAs, 32 q-rows/warp, 2 CTA/SM -------------
constexpr int fQ0   = 0;
constexpr int fKV0  = 17408;
constexpr int fKVSZ = 13312;
constexpr int fVOFF = 8704;
constexpr size_t SM_FLASH = (size_t)(17408 + 2 * 13312) * sizeof(__half); // 88064 B

__global__ __launch_bounds__(FA_THREADS, 2) void flash_attn_kernel()
{
    extern __shared__ __half hsm[];
    const int tid = threadIdx.x, lane = tid & 31, wid = tid >> 5;
    const int g = lane >> 2, t = lane & 3;
    const int lrow = lane & 15, lhi = (lane >> 4) & 1;
    const int bh = blockIdx.y, b = bh >> 4, head = bh & 15;
    const int m0 = blockIdx.x * 128;

    const __half* Qg = g_q + (size_t)bh * Ss * 128;
    const __half* Kg = g_k + (size_t)bh * Ss * 128;
    const __half* Vg = g_v + (size_t)bh * Ss * Dd;

    const uint32_t sQ = smem_u32(hsm + fQ0);

    #pragma unroll
    for (int u = 0; u < 16; ++u) {
        int idx = tid + u * FA_THREADS;
        int m = idx >> 4, q = idx & 15;
        cp16(sQ + (m * 136 + q * 8) * 2, Qg + (size_t)(m0 + m) * 128 + q * 8);
    }

    {
        int buf = tid >> 6, r = tid & 63;
        uint4* pad = reinterpret_cast<uint4*>(
            hsm + fKV0 + buf * fKVSZ + fVOFF + r * 72 + 64);
        *pad = make_uint4(0x00003C00u, 0u, 0u, 0u);
    }

    auto load_kv = [&](int kt, int buf) {
        uint32_t sK = smem_u32(hsm + fKV0 + buf * fKVSZ);
        uint32_t sV = sK + fVOFF * 2;
        const __half* kp = Kg + (size_t)kt * 64 * 128;
        const __half* vp = Vg + (size_t)kt * 64 * Dd;
        #pragma unroll
        for (int u = 0; u < 8; ++u) {
            int idx = tid + u * FA_THREADS;
            int r = idx >> 4, q = idx & 15;
            cp16(sK + (r * 136 + q * 8) * 2, kp + (size_t)r * 128 + q * 8);
        }
        #pragma unroll
        for (int u = 0; u < 4; ++u) {
            int idx = tid + u * FA_THREADS;
            int r = idx >> 3, q = idx & 7;
            cp16(sV + (r * 72 + q * 8) * 2, vp + (size_t)r * Dd + q * 8);
        }
    };
    load_kv(0, 0);
    cp_commit();

    float m_run[2][2] = {{-1e30f, -1e30f}, {-1e30f, -1e30f}};
    float acc_o[2][8][4] = {};
    float acc_l[2][4] = {};
    const int mq = wid * 32;

    constexpr int NT = Ss / 64;
    for (int kt = 0; kt < NT; ++kt) {
        const int buf = kt & 1;
        cp_wait<0>();
        __syncthreads();
        if (kt + 1 < NT) { load_kv(kt + 1, buf ^ 1); cp_commit(); }

        const uint32_t sK = smem_u32(hsm + fKV0 + buf * fKVSZ);
        const uint32_t sV = sK + fVOFF * 2;

        float acc_s[2][8][4] = {};
        #pragma unroll
        for (int ks = 0; ks < 8; ++ks) {
            uint32_t qf[2][4];
            #pragma unroll
            for (int si = 0; si < 2; ++si)
                ldsm4(qf[si], sQ + ((mq + si * 16 + lrow) * 136 + ks * 16 + lhi * 8) * 2);
            #pragma unroll
            for (int p = 0; p < 4; ++p) {
                uint32_t bf[4];
                ldsm4(bf, sK + ((p * 16 + lrow) * 136 + ks * 16 + lhi * 8) * 2);
                uint32_t b0[2] = { bf[0], bf[2] };
                uint32_t b1[2] = { bf[1], bf[3] };
                #pragma unroll
                for (int si = 0; si < 2; ++si) {
                    mma16816(acc_s[si][2 * p],     qf[si], b0);
                    mma16816(acc_s[si][2 * p + 1], qf[si], b1);
                }
            }
        }

        uint32_t pf[2][4][4];
        #pragma unroll
        for (int si = 0; si < 2; ++si) {
            float tm0 = -1e30f, tm1 = -1e30f;
            #pragma unroll
            for (int j = 0; j < 8; ++j) {
                tm0 = fmaxf(tm0, fmaxf(acc_s[si][j][0], acc_s[si][j][1]));
                tm1 = fmaxf(tm1, fmaxf(acc_s[si][j][2], acc_s[si][j][3]));
            }
            #pragma unroll
            for (int o = 1; o <= 2; o <<= 1) {
                tm0 = fmaxf(tm0, __shfl_xor_sync(0xffffffffu, tm0, o));
                tm1 = fmaxf(tm1, __shfl_xor_sync(0xffffffffu, tm1, o));
            }
            float mn0 = fmaxf(m_run[si][0], tm0), mn1 = fmaxf(m_run[si][1], tm1);
            float sc0 = ex2f(m_run[si][0] - mn0), sc1 = ex2f(m_run[si][1] - mn1);
            m_run[si][0] = mn0; m_run[si][1] = mn1;

            #pragma unroll
            for (int j = 0; j < 8; ++j) {
                acc_s[si][j][0] = ex2f(acc_s[si][j][0] - mn0);
                acc_s[si][j][1] = ex2f(acc_s[si][j][1] - mn0);
                acc_s[si][j][2] = ex2f(acc_s[si][j][2] - mn1);
                acc_s[si][j][3] = ex2f(acc_s[si][j][3] - mn1);
            }
            #pragma unroll
            for (int j = 0; j < 8; ++j) {
                acc_o[si][j][0] *= sc0; acc_o[si][j][1] *= sc0;
                acc_o[si][j][2] *= sc1; acc_o[si][j][3] *= sc1;
            }
            acc_l[si][0] *= sc0; acc_l[si][1] *= sc0;
            acc_l[si][2] *= sc1; acc_l[si][3] *= sc1;

            #pragma unroll
            for (int k2 = 0; k2 < 4; ++k2) {
                pf[si][k2][0] = h2u(__floats2half2_rn(acc_s[si][2 * k2][0],     acc_s[si][2 * k2][1]));
                pf[si][k2][1] = h2u(__floats2half2_rn(acc_s[si][2 * k2][2],     acc_s[si][2 * k2][3]));
                pf[si][k2][2] = h2u(__floats2half2_rn(acc_s[si][2 * k2 + 1][0], acc_s[si][2 * k2 + 1][1]));
                pf[si][k2][3] = h2u(__floats2half2_rn(acc_s[si][2 * k2 + 1][2], acc_s[si][2 * k2 + 1][3]));
            }
        }

        #pragma unroll
        for (int ks = 0; ks < 4; ++ks) {
            #pragma unroll
            for (int p = 0; p < 4; ++p) {
                uint32_t bf[4];
                ldsm4t4(bf, sV + ((ks * 16 + lrow) * 72 + p * 16 + lhi * 8) * 2);
                uint32_t b0[2] = { bf[0], bf[1] };
                uint32_t b1[2] = { bf[2], bf[3] };
                #pragma unroll
                for (int si = 0; si < 2; ++si) {
                    mma16816(acc_o[si][2 * p],     pf[si][ks], b0);
                    mma16816(acc_o[si][2 * p + 1], pf[si][ks], b1);
                }
            }
            uint32_t bl[2];
            ldsm2t(bl, sV + ((ks * 16 + lrow) * 72 + 64) * 2);
            #pragma unroll
            for (int si = 0; si < 2; ++si)
                mma16816(acc_l[si], pf[si][ks], bl);
        }
    }

    #pragma unroll
    for (int si = 0; si < 2; ++si) {
        float l0 = __shfl_sync(0xffffffffu, acc_l[si][0], lane & ~3);
        float l1 = __shfl_sync(0xffffffffu, acc_l[si][2], lane & ~3);
        float inv0 = 1.0f / l0, inv1 = 1.0f / l1;
        int s0 = m0 + mq + si * 16 + g;
        #pragma unroll
        for (int j = 0; j < 8; ++j) {
            int c = j * 8 + 2 * t;
            __half* o0 = g_concat + ((size_t)(b * Ss + s0)) * Hh + head * Dd + c;
            __half* o1 = g_concat + ((size_t)(b * Ss + s0 + 8)) * Hh + head * Dd + c;
            *reinterpret_cast<__half2*>(o0) =
                __floats2half2_rn(acc_o[si][j][0] * inv0, acc_o[si][j][1] * inv0);
            *reinterpret_cast<__half2*>(o1) =
                __floats2half2_rn(acc_o[si][j][2] * inv1, acc_o[si][j][3] * inv1);
        }
    }
}

// ---------------- LayerNorms ----------------------------------------------------------
__global__ __launch_bounds__(THREADS) void layernorm1_kernel(
    const float* __restrict__ gw, const float* __restrict__ bw)
{
    int row = blockIdx.x;
    const float4* rp = reinterpret_cast<const float4*>(g_tmp + (size_t)row * Hh);
    float4 v = rp[threadIdx.x];
    float s  = v.x + v.y + v.z + v.w;
    float s2 = v.x * v.x + v.y * v.y + v.z * v.z + v.w * v.w;
    #pragma unroll
    for (int o = 16; o; o >>= 1) {
        s  += __shfl_xor_sync(0xffffffffu, s,  o);
        s2 += __shfl_xor_sync(0xffffffffu, s2, o);
    }
    __shared__ float rs[8], rs2[8];
    int lane = threadIdx.x & 31, wid = threadIdx.x >> 5;
    if (lane == 0) { rs[wid] = s; rs2[wid] = s2; }
    __syncthreads();
    s = 0.f; s2 = 0.f;
    #pragma unroll
    for (int i = 0; i < 8; ++i) { s += rs[i]; s2 += rs2[i]; }
    float mu  = s  * (1.0f / Hh);
    float var = s2 * (1.0f / Hh) - mu * mu;
    float inv = rsqrtf(var + EPSLN);
    float4 g4 = reinterpret_cast<const float4*>(gw)[threadIdx.x];
    float4 b4 = reinterpret_cast<const float4*>(bw)[threadIdx.x];
    float4 o4;
    o4.x = (v.x - mu) * inv * g4.x + b4.x;
    o4.y = (v.y - mu) * inv * g4.y + b4.y;
    o4.z = (v.z - mu) * inv * g4.z + b4.z;
    o4.w = (v.w - mu) * inv * g4.w + b4.w;
    uint2 hh = make_uint2(h2u(__floats2half2_rn(o4.x, o4.y)),
                          h2u(__floats2half2_rn(o4.z, o4.w)));
    reinterpret_cast<uint2*>(g_h1h + (size_t)row * Hh)[threadIdx.x] = hh;
}

__global__ __launch_bounds__(THREADS) void layernorm2_kernel(
    const float* __restrict__ gw, const float* __restrict__ bw,
    float* __restrict__ out)
{
    int row = blockIdx.x;
    const float4* rp = reinterpret_cast<const float4*>(g_tmp + (size_t)row * Hh);
    float4 v = rp[threadIdx.x];
    float s  = v.x + v.y + v.z + v.w;
    float s2 = v.x * v.x + v.y * v.y + v.z * v.z + v.w * v.w;
    #pragma unroll
    for (int o = 16; o; o >>= 1) {
        s  += __shfl_xor_sync(0xffffffffu, s,  o);
        s2 += __shfl_xor_sync(0xffffffffu, s2, o);
    }
    __shared__ float rs[8], rs2[8];
    int lane = threadIdx.x & 31, wid = threadIdx.x >> 5;
    if (lane == 0) { rs[wid] = s; rs2[wid] = s2; }
    __syncthreads();
    s = 0.f; s2 = 0.f;
    #pragma unroll
    for (int i = 0; i < 8; ++i) { s += rs[i]; s2 += rs2[i]; }
    float mu  = s  * (1.0f / Hh);
    float var = s2 * (1.0f / Hh) - mu * mu;
    float inv = rsqrtf(var + EPSLN);
    float4 g4 = reinterpret_cast<const float4*>(gw)[threadIdx.x];
    float4 b4 = reinterpret_cast<const float4*>(bw)[threadIdx.x];
    float4 o4;
    o4.x = (v.x - mu) * inv * g4.x + b4.x;
    o4.y = (v.y - mu) * inv * g4.y + b4.y;
    o4.z = (v.z - mu) * inv * g4.z + b4.z;
    o4.w = (v.w - mu) * inv * g4.w + b4.w;
    reinterpret_cast<float4*>(out + (size_t)row * Hh)[threadIdx.x] = o4;
}

// ---------------- entry -----------------------------------------------------------------
extern "C" void kernel_launch(void* const* d_in, const int* in_sizes, int n_in,
                              void* d_out, int out_size)
{
    const float* x   = (const float*)d_in[0];
    const float* Wqr = (const float*)d_in[1];
    const float* Wqi = (const float*)d_in[2];
    const float* bqr = (const float*)d_in[3];
    const float* bqi = (const float*)d_in[4];
    const float* Wkr = (const float*)d_in[5];
    const float* Wki = (const float*)d_in[6];
    const float* bkr = (const float*)d_in[7];
    const float* bki = (const float*)d_in[8];
    const float* Wv  = (const float*)d_in[9];
    const float* bvv = (const float*)d_in[10];
    const float* pqr = (const float*)d_in[11];
    const float* pqi = (const float*)d_in[12];
    const float* pkr = (const float*)d_in[13];
    const float* pki = (const float*)d_in[14];
    const float* Wo  = (const float*)d_in[15];
    const float* bo  = (const float*)d_in[16];
    const float* W1  = (const float*)d_in[17];
    const float* b1  = (const float*)d_in[18];
    const float* W2  = (const float*)d_in[19];
    const float* b2  = (const float*)d_in[20];
    const float* g1  = (const float*)d_in[21];
    const float* be1 = (const float*)d_in[22];
    const float* g2  = (const float*)d_in[23];
    const float* be2 = (const float*)d_in[24];
    float* out = (float*)d_out;

    static bool attr_done = false;
    if (!attr_done) {
        cudaFuncSetAttribute(hproj_kernel,
            cudaFuncAttributeMaxDynamicSharedMemorySize, (int)SM_HGEMM);
        cudaFuncSetAttribute(hwo_kernel,
            cudaFuncAttributeMaxDynamicSharedMemorySize, (int)SM_HGEMM);
        cudaFuncSetAttribute(hff1_kernel,
            cudaFuncAttributeMaxDynamicSharedMemorySize, (int)SM_HGEMM);
        cudaFuncSetAttribute(hff2_kernel,
            cudaFuncAttributeMaxDynamicSharedMemorySize, (int)SM_HGEMM);
        cudaFuncSetAttribute(flash_attn_kernel,
            cudaFuncAttributeMaxDynamicSharedMemorySize, (int)SM_FLASH);
        attr_done = true;
    }

    const int U4 = THREADS * 4;
    prepass_kernel<<<(N4_TOT + U4 - 1) / U4, THREADS>>>(
        (const float4*)x, (const float4*)Wo, (const float4*)W1, (const float4*)W2,
        Wqr, Wqi, Wkr, Wki, Wv);

    hproj_kernel<<<dim3(5120 / 128, (Bb * Ss) / 128), THREADS, SM_HGEMM>>>(
        bqr, bqi, bkr, bki, bvv, pqr, pqi, pkr, pki);
    flash_attn_kernel<<<dim3(Ss / 128, Bb * Nn), FA_THREADS, SM_FLASH>>>();
    hwo_kernel<<<dim3(Hh / 128, (Bb * Ss) / 128), THREADS, SM_HGEMM>>>(bo, x);
    layernorm1_kernel<<<Bb * Ss, THREADS>>>(g1, be1);
    hff1_kernel<<<dim3(FFd / 128, (Bb * Ss) / 128), THREADS, SM_HGEMM>>>(b1);
    hff2_kernel<<<dim3(Hh / 128, (Bb * Ss) / 128), THREADS, SM_HGEMM>>>(b2);
    layernorm2_kernel<<<Bb * Ss, THREADS>>>(g2, be2, out);
}